// round 9
// baseline (speedup 1.0000x reference)
#include <cuda_runtime.h>
#include <cuda_bf16.h>
#include <cstdint>

// ---------------------------------------------------------------------------
// LGNInputLayerCell: i_in[post] += weights[s] * (inputs_t[pre[s]] > 0)
//   d_in[0] : int32  inputs_t [N_SOURCE]   (17400)
//   d_in[1] : int32  indices  [N_SYN, 2]   (post, pre) interleaved
//   d_in[2] : float  weights  [N_SYN]
//   d_in[3] : int32  n_post   (unused; out_size == n_post)
// output: float [n_post]
//
// R8 analysis: the per-lane LDG path cannot hold enough sectors in flight
// (per-SM wavefront queue ~248) to reach DRAM peak while 15M scattered REDs
// share the same L1tex queue. This version streams indices/weights with
// cp.async.bulk (TMA bulk engine, zero per-lane L1tex cost) into a 3-stage
// SMEM pipeline; the L1tex/LSU path is left almost entirely to the REDs.
// ---------------------------------------------------------------------------

#define MASK_WORDS_MAX 2048     // 65536 sources capacity (17400 used -> 544 words)
__device__ unsigned int g_active_mask[MASK_WORDS_MAX];

#define CHUNK   1024            // synapses per pipeline stage
#define STAGES  3
#define THREADS 256
// per stage: indices 8192 B + weights 4096 B = 12288 B
#define IDX_BYTES (CHUNK * 8)
#define W_BYTES   (CHUNK * 4)
#define TX_BYTES  (IDX_BYTES + W_BYTES)

// ---------------- inline PTX helpers ----------------
__device__ __forceinline__ uint32_t smem_u32(const void* p) {
    uint32_t a;
    asm("{ .reg .u64 t; cvta.to.shared.u64 t, %1; cvt.u32.u64 %0, t; }"
        : "=r"(a) : "l"(p));
    return a;
}

#define MBAR_INIT(addr, cnt) \
    asm volatile("mbarrier.init.shared.b64 [%0], %1;" :: "r"(addr), "r"(cnt) : "memory")
#define MBAR_EXPECT_TX(addr, bytes) \
    asm volatile("mbarrier.arrive.expect_tx.shared.b64 _, [%0], %1;" \
                 :: "r"(addr), "r"(bytes) : "memory")
#define MBAR_ARRIVE(addr) \
    asm volatile("mbarrier.arrive.shared.b64 _, [%0];" :: "r"(addr) : "memory")

#define BULK_G2S(dst_smem, src_gmem, bytes, mbar) \
    asm volatile("cp.async.bulk.shared::cta.global.mbarrier::complete_tx::bytes " \
                 "[%0], [%1], %2, [%3];" \
                 :: "r"(dst_smem), "l"(src_gmem), "r"(bytes), "r"(mbar) : "memory")

// Acquire wait (consumer: generic LDS follows)
#define MBAR_WAIT_ACQ(addr, parity) do {                                        \
    uint32_t _m = (addr); uint32_t _p = (parity); uint32_t _done;               \
    asm volatile("{\n\t.reg .pred p;\n\t"                                       \
        "mbarrier.try_wait.parity.acquire.cta.shared::cta.b64 p, [%1], %2;\n\t" \
        "selp.b32 %0, 1, 0, p;\n\t}"                                            \
        : "=r"(_done) : "r"(_m), "r"(_p) : "memory");                           \
    if (!_done) {                                                               \
        asm volatile("{\n\t.reg .pred P1;\n\t"                                  \
            "WLA_%=:\n\t"                                                       \
            "mbarrier.try_wait.parity.acquire.cta.shared::cta.b64 P1, [%0], %1, 0x989680;\n\t" \
            "@P1 bra.uni WDA_%=;\n\t"                                           \
            "bra.uni WLA_%=;\n\t"                                               \
            "WDA_%=:\n\t}" :: "r"(_m), "r"(_p) : "memory");                     \
    }                                                                           \
} while (0)

// Relaxed wait (producer: post-wait SMEM accesses are async-proxy TMA only)
#define MBAR_WAIT_RLX(addr, parity) do {                                        \
    uint32_t _m = (addr); uint32_t _p = (parity); uint32_t _done;               \
    asm volatile("{\n\t.reg .pred p;\n\t"                                       \
        "mbarrier.try_wait.parity.relaxed.cta.shared::cta.b64 p, [%1], %2, 0x989680;\n\t" \
        "selp.b32 %0, 1, 0, p;\n\t}"                                            \
        : "=r"(_done) : "r"(_m), "r"(_p) : "memory");                           \
    if (!_done) {                                                               \
        asm volatile("{\n\t.reg .pred P1;\n\t"                                  \
            "WLR_%=:\n\t"                                                       \
            "mbarrier.try_wait.parity.relaxed.cta.shared::cta.b64 P1, [%0], %1, 0x989680;\n\t" \
            "@P1 bra.uni WDR_%=;\n\t"                                           \
            "bra.uni WLR_%=;\n\t"                                               \
            "WDR_%=:\n\t}" :: "r"(_m), "r"(_p) : "memory");                     \
    }                                                                           \
} while (0)

// ---------------------------------------------------------------------------
// Prologue: build active bitmask (ballot) + zero the poisoned output.
// ---------------------------------------------------------------------------
__global__ void prologue_kernel(const int* __restrict__ inputs_t,
                                int n_source,
                                float* __restrict__ out, int n_post) {
    const int i = blockIdx.x * blockDim.x + threadIdx.x;

    const int n_src32 = (n_source + 31) & ~31;
    if (i < n_src32) {
        int v = (i < n_source) ? inputs_t[i] : 0;
        unsigned int b = __ballot_sync(0xffffffffu, v > 0);
        if ((threadIdx.x & 31) == 0) g_active_mask[i >> 5] = b;
    }

    const int base = i << 2;
    if (base + 3 < n_post) {
        *reinterpret_cast<float4*>(out + base) = make_float4(0.f, 0.f, 0.f, 0.f);
    } else if (base < n_post) {
        for (int j = base; j < n_post; ++j) out[j] = 0.0f;
    }
}

// ---------------------------------------------------------------------------
// Main kernel: TMA-bulk-fed 3-stage pipeline scatter-reduce.
// Thread 0 = TMA producer; all 256 threads = consumers (4 synapses each/chunk).
// ---------------------------------------------------------------------------
__global__ __launch_bounds__(THREADS)
void seg_sum_tma_kernel(const int* __restrict__ indices,
                        const float* __restrict__ weights,
                        float* __restrict__ out,
                        int n_chunks, int n_words) {
    __shared__ unsigned int s_mask[MASK_WORDS_MAX];                    // 8 KB
    __shared__ __align__(16) int                s_idx[STAGES][CHUNK * 2]; // 24 KB
    __shared__ __align__(16) float              s_w[STAGES][CHUNK];       // 12 KB
    __shared__ __align__(8)  unsigned long long s_bar[2 * STAGES];        // full/empty

    const int tid = threadIdx.x;
    const uint32_t bar_base = smem_u32(s_bar);

    if (tid == 0) {
        #pragma unroll
        for (int s = 0; s < STAGES; ++s) {
            MBAR_INIT(bar_base + 16 * s, 1);            // full: 1 arrival + tx bytes
            MBAR_INIT(bar_base + 16 * s + 8, THREADS);  // empty: all threads arrive
        }
    }
    // stage the active mask in SMEM
    {
        const int n_w4 = (n_words + 3) >> 2;
        int4* s4 = reinterpret_cast<int4*>(s_mask);
        const int4* g4 = reinterpret_cast<const int4*>(g_active_mask);
        for (int w = tid; w < n_w4; w += THREADS) s4[w] = g4[w];
    }
    __syncthreads();

    // contiguous chunk range for this block
    const int per = (n_chunks + gridDim.x - 1) / gridDim.x;
    const int c0  = blockIdx.x * per;
    int c1 = c0 + per; if (c1 > n_chunks) c1 = n_chunks;
    const int iters = c1 - c0;
    if (iters <= 0) return;

    // producer cursor (phase 1: first empty-wait on each fresh barrier passes)
    int prod_stage = 0, prod_phase = 1;
    // consumer cursor
    int cons_stage = 0, cons_phase = 0;

    // prime the pipeline: fill up to STAGES buffers
    if (tid == 0) {
        const int prime = (iters < STAGES) ? iters : STAGES;
        for (int j = 0; j < prime; ++j) {
            MBAR_WAIT_RLX(bar_base + 16 * prod_stage + 8, prod_phase);
            MBAR_EXPECT_TX(bar_base + 16 * prod_stage, TX_BYTES);
            const size_t c = (size_t)(c0 + j);
            BULK_G2S(smem_u32(&s_idx[prod_stage][0]), indices + c * (CHUNK * 2),
                     IDX_BYTES, bar_base + 16 * prod_stage);
            BULK_G2S(smem_u32(&s_w[prod_stage][0]), weights + c * CHUNK,
                     W_BYTES, bar_base + 16 * prod_stage);
            if (++prod_stage == STAGES) { prod_stage = 0; prod_phase ^= 1; }
        }
    }

    for (int i = 0; i < iters; ++i) {
        // ---- consume chunk i ----
        MBAR_WAIT_ACQ(bar_base + 16 * cons_stage, cons_phase);

        const int4* ip = reinterpret_cast<const int4*>(&s_idx[cons_stage][tid * 8]);
        int4   a = ip[0];                 // (post0, pre0, post1, pre1)
        int4   b = ip[1];                 // (post2, pre2, post3, pre3)
        float4 w = *reinterpret_cast<const float4*>(&s_w[cons_stage][tid * 4]);

        const unsigned int m0 = s_mask[((unsigned)a.y) >> 5];
        const unsigned int m1 = s_mask[((unsigned)a.w) >> 5];
        const unsigned int m2 = s_mask[((unsigned)b.y) >> 5];
        const unsigned int m3 = s_mask[((unsigned)b.w) >> 5];

        if ((m0 >> (a.y & 31)) & 1u) atomicAdd(out + a.x, w.x);
        if ((m1 >> (a.w & 31)) & 1u) atomicAdd(out + a.z, w.y);
        if ((m2 >> (b.y & 31)) & 1u) atomicAdd(out + b.x, w.z);
        if ((m3 >> (b.w & 31)) & 1u) atomicAdd(out + b.z, w.w);

        MBAR_ARRIVE(bar_base + 16 * cons_stage + 8);   // data consumed into regs
        if (++cons_stage == STAGES) { cons_stage = 0; cons_phase ^= 1; }

        // ---- produce chunk i + STAGES ----
        if (tid == 0 && i + STAGES < iters) {
            MBAR_WAIT_RLX(bar_base + 16 * prod_stage + 8, prod_phase);
            MBAR_EXPECT_TX(bar_base + 16 * prod_stage, TX_BYTES);
            const size_t c = (size_t)(c0 + i + STAGES);
            BULK_G2S(smem_u32(&s_idx[prod_stage][0]), indices + c * (CHUNK * 2),
                     IDX_BYTES, bar_base + 16 * prod_stage);
            BULK_G2S(smem_u32(&s_w[prod_stage][0]), weights + c * CHUNK,
                     W_BYTES, bar_base + 16 * prod_stage);
            if (++prod_stage == STAGES) { prod_stage = 0; prod_phase ^= 1; }
        }
    }
}

// Tail for n_syn % CHUNK (896 synapses at N_SYN = 30M).
__global__ void seg_sum_tail_kernel(const int2* __restrict__ idx2,
                                    const float* __restrict__ wts,
                                    float* __restrict__ out,
                                    int start, int n_syn) {
    for (int i = start + blockIdx.x * blockDim.x + threadIdx.x;
         i < n_syn; i += gridDim.x * blockDim.x) {
        int2 p = __ldg(&idx2[i]);     // (post, pre)
        unsigned int m = g_active_mask[((unsigned)p.y) >> 5];
        if ((m >> (p.y & 31)) & 1u) atomicAdd(out + p.x, __ldg(&wts[i]));
    }
}

extern "C" void kernel_launch(void* const* d_in, const int* in_sizes, int n_in,
                              void* d_out, int out_size) {
    const int*   inputs_t = (const int*)d_in[0];
    const int*   indices  = (const int*)d_in[1];
    const float* weights  = (const float*)d_in[2];
    float*       out      = (float*)d_out;

    const int n_source = in_sizes[0];
    const int n_syn    = in_sizes[2];
    const int n_post   = out_size;

    // 1) fused prologue: bitmask + output zeroing
    {
        const int n_src32   = (n_source + 31) & ~31;
        const int n_zero_th = (n_post + 3) >> 2;
        const int n_thr     = (n_src32 > n_zero_th) ? n_src32 : n_zero_th;
        prologue_kernel<<<(n_thr + 255) / 256, 256>>>(inputs_t, n_source, out, n_post);
    }

    // 2) TMA-pipelined scatter-reduce over full chunks
    const int n_words  = (n_source + 31) >> 5;   // 544 (< 2048)
    const int n_chunks = n_syn / CHUNK;          // 29296 at N_SYN=30M
    if (n_chunks > 0) {
        int blocks = 148 * 5;                    // ~5 blocks/SM (SMEM-limited)
        if (blocks > n_chunks) blocks = n_chunks;
        seg_sum_tma_kernel<<<blocks, THREADS>>>(indices, weights, out,
                                                n_chunks, n_words);
    }

    // 3) tail
    const int done = n_chunks * CHUNK;
    if (done < n_syn) {
        seg_sum_tail_kernel<<<1, 256>>>(
            (const int2*)indices, weights, out, done, n_syn);
    }
}

// round 11
// speedup vs baseline: 1.0595x; 1.0595x over previous
#include <cuda_runtime.h>
#include <cuda_bf16.h>
#include <cstdint>

// ---------------------------------------------------------------------------
// LGNInputLayerCell: i_in[post] += weights[s] * (inputs_t[pre[s]] > 0)
//   d_in[0] : int32  inputs_t [N_SOURCE]   (17400)
//   d_in[1] : int32  indices  [N_SYN, 2]   (post, pre) interleaved
//   d_in[2] : float  weights  [N_SYN]
//   d_in[3] : int32  n_post   (unused; out_size == n_post)
// output: float [n_post]
//
// TMA v2: cp.async.bulk streams indices+weights into a 3-stage SMEM ring
// (zero per-lane L1tex cost for the 360MB stream). Stage recycling is done
// with ONE __syncthreads per iteration instead of an empty mbarrier, and each
// thread consumes 8 synapses per iteration so sync cost is amortized.
// The L1tex/LSU path is left almost entirely to the scattered REDs.
// ---------------------------------------------------------------------------

#define MASK_WORDS_MAX 2048     // 65536 sources capacity (17400 -> 544 words)
__device__ unsigned int g_active_mask[MASK_WORDS_MAX];

#define THREADS 512
#define CHUNK   4096            // synapses per stage (8 per thread)
#define STAGES  3
#define IDX_BYTES (CHUNK * 8)   // 32 KB
#define W_BYTES   (CHUNK * 4)   // 16 KB
#define TX_BYTES  (IDX_BYTES + W_BYTES)

// dynamic SMEM layout (bytes):
//   [0, 64)                       : mbarriers (STAGES x 8B, padded)
//   [64, 64+8192)                 : active mask
//   [MOFF_IDX, +STAGES*32KB)      : index stages (int4[2048] each)
//   [MOFF_W,   +STAGES*16KB)      : weight stages (float2[2048] each)
#define MOFF_MASK 64
#define MOFF_IDX  (MOFF_MASK + MASK_WORDS_MAX * 4)
#define MOFF_W    (MOFF_IDX + STAGES * IDX_BYTES)
#define SMEM_TOTAL (MOFF_W + STAGES * W_BYTES)

// ---------------- inline PTX helpers ----------------
__device__ __forceinline__ uint32_t smem_u32(const void* p) {
    uint32_t a;
    asm("{ .reg .u64 t; cvta.to.shared.u64 t, %1; cvt.u32.u64 %0, t; }"
        : "=r"(a) : "l"(p));
    return a;
}

#define MBAR_INIT(addr, cnt) \
    asm volatile("mbarrier.init.shared.b64 [%0], %1;" :: "r"(addr), "r"(cnt) : "memory")
#define MBAR_EXPECT_TX(addr, bytes) \
    asm volatile("mbarrier.arrive.expect_tx.shared.b64 _, [%0], %1;" \
                 :: "r"(addr), "r"(bytes) : "memory")
#define BULK_G2S(dst_smem, src_gmem, bytes, mbar) \
    asm volatile("cp.async.bulk.shared::cta.global.mbarrier::complete_tx::bytes " \
                 "[%0], [%1], %2, [%3];" \
                 :: "r"(dst_smem), "l"(src_gmem), "r"(bytes), "r"(mbar) : "memory")

// Acquire wait (consumer: generic LDS follows)
#define MBAR_WAIT_ACQ(addr, parity) do {                                        \
    uint32_t _m = (addr); uint32_t _p = (parity); uint32_t _done;               \
    asm volatile("{\n\t.reg .pred p;\n\t"                                       \
        "mbarrier.try_wait.parity.acquire.cta.shared::cta.b64 p, [%1], %2;\n\t" \
        "selp.b32 %0, 1, 0, p;\n\t}"                                            \
        : "=r"(_done) : "r"(_m), "r"(_p) : "memory");                           \
    if (!_done) {                                                               \
        asm volatile("{\n\t.reg .pred P1;\n\t"                                  \
            "WLA_%=:\n\t"                                                       \
            "mbarrier.try_wait.parity.acquire.cta.shared::cta.b64 P1, [%0], %1, 0x989680;\n\t" \
            "@P1 bra.uni WDA_%=;\n\t"                                           \
            "bra.uni WLA_%=;\n\t"                                               \
            "WDA_%=:\n\t}" :: "r"(_m), "r"(_p) : "memory");                     \
    }                                                                           \
} while (0)

// ---------------------------------------------------------------------------
// Prologue: build active bitmask (ballot) + zero the poisoned output.
// ---------------------------------------------------------------------------
__global__ void prologue_kernel(const int* __restrict__ inputs_t,
                                int n_source,
                                float* __restrict__ out, int n_post) {
    const int i = blockIdx.x * blockDim.x + threadIdx.x;

    const int n_src32 = (n_source + 31) & ~31;
    if (i < n_src32) {
        int v = (i < n_source) ? inputs_t[i] : 0;
        unsigned int b = __ballot_sync(0xffffffffu, v > 0);
        if ((threadIdx.x & 31) == 0) g_active_mask[i >> 5] = b;
    }

    const int base = i << 2;
    if (base + 3 < n_post) {
        *reinterpret_cast<float4*>(out + base) = make_float4(0.f, 0.f, 0.f, 0.f);
    } else if (base < n_post) {
        for (int j = base; j < n_post; ++j) out[j] = 0.0f;
    }
}

// ---------------------------------------------------------------------------
// Main kernel: TMA-bulk 3-stage ring, __syncthreads-recycled.
// ---------------------------------------------------------------------------
__global__ __launch_bounds__(THREADS)
void seg_sum_tma_kernel(const int* __restrict__ indices,
                        const float* __restrict__ weights,
                        float* __restrict__ out,
                        int n_chunks, int n_words) {
    extern __shared__ __align__(16) unsigned char smem[];
    unsigned int* s_mask = reinterpret_cast<unsigned int*>(smem + MOFF_MASK);
    const uint32_t bar_base = smem_u32(smem);           // barriers at offset 0

    const int tid = threadIdx.x;

    if (tid == 0) {
        #pragma unroll
        for (int s = 0; s < STAGES; ++s) MBAR_INIT(bar_base + 8 * s, 1);
    }
    // stage the active mask in SMEM
    {
        const int n_w4 = (n_words + 3) >> 2;
        int4* s4 = reinterpret_cast<int4*>(s_mask);
        const int4* g4 = reinterpret_cast<const int4*>(g_active_mask);
        for (int w = tid; w < n_w4; w += THREADS) s4[w] = g4[w];
    }
    __syncthreads();

    // contiguous chunk range for this block
    const int per = (n_chunks + gridDim.x - 1) / gridDim.x;
    const int c0  = blockIdx.x * per;
    int c1 = c0 + per; if (c1 > n_chunks) c1 = n_chunks;
    const int iters = c1 - c0;
    if (iters <= 0) return;

    // prime the ring
    if (tid == 0) {
        const int prime = (iters < STAGES) ? iters : STAGES;
        for (int j = 0; j < prime; ++j) {
            const uint32_t mb = bar_base + 8 * j;
            MBAR_EXPECT_TX(mb, TX_BYTES);
            const size_t c = (size_t)(c0 + j);
            BULK_G2S(smem_u32(smem + MOFF_IDX + j * IDX_BYTES),
                     indices + c * (CHUNK * 2), IDX_BYTES, mb);
            BULK_G2S(smem_u32(smem + MOFF_W + j * W_BYTES),
                     weights + c * CHUNK, W_BYTES, mb);
        }
    }

    for (int i = 0; i < iters; ++i) {
        const int s = i % STAGES;
        const int phase = (i / STAGES) & 1;

        MBAR_WAIT_ACQ(bar_base + 8 * s, phase);

        const int4*   ip = reinterpret_cast<const int4*>(smem + MOFF_IDX + s * IDX_BYTES);
        const float2* wp = reinterpret_cast<const float2*>(smem + MOFF_W + s * W_BYTES);

        // conflict-free: lane-consecutive int4 / float2, 4 slices of 512
        int4   a0 = ip[tid];            float2 w0 = wp[tid];
        int4   a1 = ip[tid + 512];      float2 w1 = wp[tid + 512];
        int4   a2 = ip[tid + 1024];     float2 w2 = wp[tid + 1024];
        int4   a3 = ip[tid + 1536];     float2 w3 = wp[tid + 1536];

        const unsigned int m0 = s_mask[((unsigned)a0.y) >> 5];
        const unsigned int m1 = s_mask[((unsigned)a0.w) >> 5];
        const unsigned int m2 = s_mask[((unsigned)a1.y) >> 5];
        const unsigned int m3 = s_mask[((unsigned)a1.w) >> 5];
        const unsigned int m4 = s_mask[((unsigned)a2.y) >> 5];
        const unsigned int m5 = s_mask[((unsigned)a2.w) >> 5];
        const unsigned int m6 = s_mask[((unsigned)a3.y) >> 5];
        const unsigned int m7 = s_mask[((unsigned)a3.w) >> 5];

        if ((m0 >> (a0.y & 31)) & 1u) atomicAdd(out + a0.x, w0.x);
        if ((m1 >> (a0.w & 31)) & 1u) atomicAdd(out + a0.z, w0.y);
        if ((m2 >> (a1.y & 31)) & 1u) atomicAdd(out + a1.x, w1.x);
        if ((m3 >> (a1.w & 31)) & 1u) atomicAdd(out + a1.z, w1.y);
        if ((m4 >> (a2.y & 31)) & 1u) atomicAdd(out + a2.x, w2.x);
        if ((m5 >> (a2.w & 31)) & 1u) atomicAdd(out + a2.z, w2.y);
        if ((m6 >> (a3.y & 31)) & 1u) atomicAdd(out + a3.x, w3.x);
        if ((m7 >> (a3.w & 31)) & 1u) atomicAdd(out + a3.z, w3.y);

        // everyone has consumed stage s (values live in registers) ->
        // safe for t0 to refill it for iteration i+STAGES.
        __syncthreads();

        if (tid == 0 && i + STAGES < iters) {
            const uint32_t mb = bar_base + 8 * s;
            MBAR_EXPECT_TX(mb, TX_BYTES);
            const size_t c = (size_t)(c0 + i + STAGES);
            BULK_G2S(smem_u32(smem + MOFF_IDX + s * IDX_BYTES),
                     indices + c * (CHUNK * 2), IDX_BYTES, mb);
            BULK_G2S(smem_u32(smem + MOFF_W + s * W_BYTES),
                     weights + c * CHUNK, W_BYTES, mb);
        }
    }
}

// Tail for n_syn % CHUNK (896 synapses at N_SYN = 30M).
__global__ void seg_sum_tail_kernel(const int2* __restrict__ idx2,
                                    const float* __restrict__ wts,
                                    float* __restrict__ out,
                                    int start, int n_syn) {
    int i = start + blockIdx.x * blockDim.x + threadIdx.x;
    if (i >= n_syn) return;
    int2 p = __ldg(&idx2[i]);     // (post, pre)
    unsigned int m = g_active_mask[((unsigned)p.y) >> 5];
    if ((m >> (p.y & 31)) & 1u) atomicAdd(out + p.x, __ldg(&wts[i]));
}

extern "C" void kernel_launch(void* const* d_in, const int* in_sizes, int n_in,
                              void* d_out, int out_size) {
    const int*   inputs_t = (const int*)d_in[0];
    const int*   indices  = (const int*)d_in[1];
    const float* weights  = (const float*)d_in[2];
    float*       out      = (float*)d_out;

    const int n_source = in_sizes[0];
    const int n_syn    = in_sizes[2];
    const int n_post   = out_size;

    // allow 152KB dynamic SMEM (idempotent; not a stream op, capture-safe)
    static bool attr_set = false;
    if (!attr_set) {
        cudaFuncSetAttribute(seg_sum_tma_kernel,
                             cudaFuncAttributeMaxDynamicSharedMemorySize,
                             SMEM_TOTAL);
        attr_set = true;
    }

    // 1) fused prologue: bitmask + output zeroing
    {
        const int n_src32   = (n_source + 31) & ~31;
        const int n_zero_th = (n_post + 3) >> 2;
        const int n_thr     = (n_src32 > n_zero_th) ? n_src32 : n_zero_th;
        prologue_kernel<<<(n_thr + 255) / 256, 256>>>(inputs_t, n_source, out, n_post);
    }

    // 2) TMA-pipelined scatter-reduce over full chunks
    const int n_words  = (n_source + 31) >> 5;   // 544 (< 2048)
    const int n_chunks = n_syn / CHUNK;          // 7324 at N_SYN=30M
    if (n_chunks > 0) {
        int blocks = 148;                        // 1 block/SM (152KB SMEM)
        if (blocks > n_chunks) blocks = n_chunks;
        seg_sum_tma_kernel<<<blocks, THREADS, SMEM_TOTAL>>>(
            indices, weights, out, n_chunks, n_words);
    }

    // 3) tail
    const int done = n_chunks * CHUNK;
    if (done < n_syn) {
        const int rem = n_syn - done;
        seg_sum_tail_kernel<<<(rem + 255) / 256, 256>>>(
            (const int2*)indices, weights, out, done, n_syn);
    }
}

// round 13
// speedup vs baseline: 1.1910x; 1.1242x over previous
#include <cuda_runtime.h>
#include <cuda_bf16.h>
#include <cstdint>

// ---------------------------------------------------------------------------
// LGNInputLayerCell: i_in[post] += weights[s] * (inputs_t[pre[s]] > 0)
//   d_in[0] : int32  inputs_t [N_SOURCE]   (17400)
//   d_in[1] : int32  indices  [N_SYN, 2]   (post, pre) interleaved
//   d_in[2] : float  weights  [N_SYN]
//   d_in[3] : int32  n_post   (unused; out_size == n_post)
// output: float [n_post]
//
// R12 = R11 resubmitted after infra failure (container acquisition died;
// kernel never ran). Flat-LDG structure (proven fastest) + L2 evict-first
// policy on the 360MB read-once stream so the 800KB `out` array stays
// L2-resident for the 15M scattered REDs. Tail folded into the main kernel.
// ---------------------------------------------------------------------------

#define MASK_WORDS_MAX 2048     // 65536 sources capacity (17400 -> 544 words)
__device__ unsigned int g_active_mask[MASK_WORDS_MAX];

#define THREADS 512

// ---- L2 evict-first streaming loads (createpolicy + cache_hint) ----
__device__ __forceinline__ uint64_t make_policy_ef() {
    uint64_t pol;
    asm("createpolicy.fractional.L2::evict_first.b64 %0, 1.0;" : "=l"(pol));
    return pol;
}
__device__ __forceinline__ int4 ldg_ef_i4(const int4* p, uint64_t pol) {
    int4 v;
    asm volatile("ld.global.nc.L2::cache_hint.v4.s32 {%0,%1,%2,%3}, [%4], %5;"
                 : "=r"(v.x), "=r"(v.y), "=r"(v.z), "=r"(v.w)
                 : "l"(p), "l"(pol));
    return v;
}
__device__ __forceinline__ float4 ldg_ef_f4(const float4* p, uint64_t pol) {
    float4 v;
    asm volatile("ld.global.nc.L2::cache_hint.v4.f32 {%0,%1,%2,%3}, [%4], %5;"
                 : "=f"(v.x), "=f"(v.y), "=f"(v.z), "=f"(v.w)
                 : "l"(p), "l"(pol));
    return v;
}

// ---------------------------------------------------------------------------
// Prologue: build active bitmask (ballot) + zero the poisoned output.
// ---------------------------------------------------------------------------
__global__ void prologue_kernel(const int* __restrict__ inputs_t,
                                int n_source,
                                float* __restrict__ out, int n_post) {
    const int i = blockIdx.x * blockDim.x + threadIdx.x;

    const int n_src32 = (n_source + 31) & ~31;
    if (i < n_src32) {
        int v = (i < n_source) ? inputs_t[i] : 0;
        unsigned int b = __ballot_sync(0xffffffffu, v > 0);
        if ((threadIdx.x & 31) == 0) g_active_mask[i >> 5] = b;
    }

    const int base = i << 2;
    if (base + 3 < n_post) {
        *reinterpret_cast<float4*>(out + base) = make_float4(0.f, 0.f, 0.f, 0.f);
    } else if (base < n_post) {
        for (int j = base; j < n_post; ++j) out[j] = 0.0f;
    }
}

// ---------------------------------------------------------------------------
// Main scatter-reduce: flat grid, 8 synapses/thread.
//   4x int4 + 2x float4, front-batched (6 independent LDG.128, L2 evict-first)
// Active mask staged in SMEM; inactive synapses skip the RED entirely.
// Tail (last partial group) handled by a scalar fallback in-kernel.
// ---------------------------------------------------------------------------
__global__ __launch_bounds__(THREADS)
void seg_sum_kernel(const int* __restrict__ indices,
                    const float* __restrict__ weights,
                    float* __restrict__ out,
                    int n_syn, int n_words) {
    __shared__ unsigned int s_mask[MASK_WORDS_MAX];
    {
        const int n_w4 = (n_words + 3) >> 2;
        int4* s4 = reinterpret_cast<int4*>(s_mask);
        const int4* g4 = reinterpret_cast<const int4*>(g_active_mask);
        for (int w = threadIdx.x; w < n_w4; w += THREADS) s4[w] = g4[w];
    }
    __syncthreads();

    const int i    = blockIdx.x * blockDim.x + threadIdx.x;
    const int base = i << 3;                   // 8 synapses per thread
    if (base >= n_syn) return;

    const uint64_t pol = make_policy_ef();

    if (base + 8 <= n_syn) {
        const int4*   idx4 = reinterpret_cast<const int4*>(indices);
        const float4* w4   = reinterpret_cast<const float4*>(weights);

        // 6 independent streaming loads, front-batched, L2 evict-first.
        int4   a0 = ldg_ef_i4(&idx4[4 * i + 0], pol);  // (post0,pre0,post1,pre1)
        int4   a1 = ldg_ef_i4(&idx4[4 * i + 1], pol);
        int4   a2 = ldg_ef_i4(&idx4[4 * i + 2], pol);
        int4   a3 = ldg_ef_i4(&idx4[4 * i + 3], pol);
        float4 w0 = ldg_ef_f4(&w4[2 * i + 0], pol);
        float4 w1 = ldg_ef_f4(&w4[2 * i + 1], pol);

        const unsigned int m0 = s_mask[((unsigned)a0.y) >> 5];
        const unsigned int m1 = s_mask[((unsigned)a0.w) >> 5];
        const unsigned int m2 = s_mask[((unsigned)a1.y) >> 5];
        const unsigned int m3 = s_mask[((unsigned)a1.w) >> 5];
        const unsigned int m4 = s_mask[((unsigned)a2.y) >> 5];
        const unsigned int m5 = s_mask[((unsigned)a2.w) >> 5];
        const unsigned int m6 = s_mask[((unsigned)a3.y) >> 5];
        const unsigned int m7 = s_mask[((unsigned)a3.w) >> 5];

        if ((m0 >> (a0.y & 31)) & 1u) atomicAdd(out + a0.x, w0.x);
        if ((m1 >> (a0.w & 31)) & 1u) atomicAdd(out + a0.z, w0.y);
        if ((m2 >> (a1.y & 31)) & 1u) atomicAdd(out + a1.x, w0.z);
        if ((m3 >> (a1.w & 31)) & 1u) atomicAdd(out + a1.z, w0.w);
        if ((m4 >> (a2.y & 31)) & 1u) atomicAdd(out + a2.x, w1.x);
        if ((m5 >> (a2.w & 31)) & 1u) atomicAdd(out + a2.z, w1.y);
        if ((m6 >> (a3.y & 31)) & 1u) atomicAdd(out + a3.x, w1.z);
        if ((m7 >> (a3.w & 31)) & 1u) atomicAdd(out + a3.z, w1.w);
    } else {
        // scalar tail (last partial group of < 8 synapses)
        for (int j = base; j < n_syn; ++j) {
            int post = indices[2 * j];
            int pre  = indices[2 * j + 1];
            unsigned int m = s_mask[((unsigned)pre) >> 5];
            if ((m >> (pre & 31)) & 1u) atomicAdd(out + post, weights[j]);
        }
    }
}

extern "C" void kernel_launch(void* const* d_in, const int* in_sizes, int n_in,
                              void* d_out, int out_size) {
    const int*   inputs_t = (const int*)d_in[0];
    const int*   indices  = (const int*)d_in[1];
    const float* weights  = (const float*)d_in[2];
    float*       out      = (float*)d_out;

    const int n_source = in_sizes[0];
    const int n_syn    = in_sizes[2];
    const int n_post   = out_size;

    // 1) fused prologue: bitmask + output zeroing
    {
        const int n_src32   = (n_source + 31) & ~31;
        const int n_zero_th = (n_post + 3) >> 2;
        const int n_thr     = (n_src32 > n_zero_th) ? n_src32 : n_zero_th;
        prologue_kernel<<<(n_thr + 255) / 256, 256>>>(inputs_t, n_source, out, n_post);
    }

    // 2) scatter-reduce: flat grid, 8 synapses/thread, tail handled in-kernel
    const int n_words = (n_source + 31) >> 5;   // 544 (< 2048)
    const int groups  = (n_syn + 7) >> 3;
    if (groups > 0) {
        seg_sum_kernel<<<(groups + THREADS - 1) / THREADS, THREADS>>>(
            indices, weights, out, n_syn, n_words);
    }
}